// round 8
// baseline (speedup 1.0000x reference)
#include <cuda_runtime.h>
#include <cuda_fp16.h>
#include <cstdint>

#define B_     4096
#define N_IN   512
#define H1     1536
#define H2     1536
#define N_OUT  512
#define NODES  3584          // N_IN + H1 + H2
#define CAP    128           // bucket capacity per dst (Poisson(32), max ~66)
#define TBLOCKS 2048         // transpose blocks in fused setup kernel (16 x 128)

typedef unsigned long long u64;

// ---------------- static device scratch (no allocations) ----------------
__device__ __align__(16) __half g_nvTh[NODES * B_];      // 29.4 MB, L2-resident
__device__ __align__(16) float  g_outT[N_OUT * B_];      //  8.4 MB
__device__ int  g_cnt[NODES];       // zero at load; re-zeroed each call by transpose_out
__device__ __align__(16) int2 g_bpack[NODES * CAP];      // (src, w-bits)

// ---------------- packed f32x2 helpers ----------------
__device__ __forceinline__ u64 pack2(float x, float y) {
    u64 r; asm("mov.b64 %0, {%1, %2};" : "=l"(r) : "f"(x), "f"(y)); return r;
}
__device__ __forceinline__ float2 unpack2(u64 v) {
    float2 f; asm("mov.b64 {%0, %1}, %2;" : "=f"(f.x), "=f"(f.y) : "l"(v)); return f;
}
__device__ __forceinline__ void ffma2(u64& acc, u64 a, u64 b) {
    asm("fma.rn.f32x2 %0, %1, %2, %0;" : "+l"(acc) : "l"(a), "l"(b));
}
__device__ __forceinline__ u64 cvt2(uint32_t h2) {
    float2 f = __half22float2(*reinterpret_cast<const __half2*>(&h2));
    return pack2(f.x, f.y);
}

// ---------------- fused setup: transpose x -> fp16 nvT  +  bucket build ----
__global__ void setup_kernel(const float* __restrict__ x,
                             const int* __restrict__ src0, const int* __restrict__ dst0,
                             const float* __restrict__ w0, int E1,
                             const int* __restrict__ src1, const int* __restrict__ dst1,
                             const float* __restrict__ w1, int E2,
                             const int* __restrict__ src2, const int* __restrict__ dst2,
                             const float* __restrict__ w2, int E3) {
    const int tid = threadIdx.x;
    if (blockIdx.x < TBLOCKS) {
        __shared__ float tile[32][33];
        const int bx = (blockIdx.x & 15) * 32;   // node dim
        const int by = (blockIdx.x >> 4) * 32;   // batch dim
        const int tx = tid & 31, ty = tid >> 5;  // 32 x 8
#pragma unroll
        for (int i = 0; i < 32; i += 8)
            tile[ty + i][tx] = x[(size_t)(by + ty + i) * N_IN + bx + tx];
        __syncthreads();
#pragma unroll
        for (int i = 0; i < 32; i += 8)
            g_nvTh[(size_t)(bx + ty + i) * B_ + by + tx] = __float2half(tile[tx][ty + i]);
        return;
    }
    // ---- bucket part: 4 consecutive edges per thread ----
    int i0 = ((blockIdx.x - TBLOCKS) * 256 + tid) * 4;
    const int Etot = E1 + E2 + E3;
    if (i0 >= Etot) return;
    const int *sp, *dp; const float* wp; int dbase, j0;
    if (i0 < E1)           { sp = src0; dp = dst0; wp = w0; dbase = 0;       j0 = i0; }
    else if (i0 < E1 + E2) { sp = src1; dp = dst1; wp = w1; dbase = H1;      j0 = i0 - E1; }
    else                   { sp = src2; dp = dst2; wp = w2; dbase = H1 + H2; j0 = i0 - E1 - E2; }
    int4   s = *reinterpret_cast<const int4*>(sp + j0);
    int4   d = *reinterpret_cast<const int4*>(dp + j0);
    float4 w = *reinterpret_cast<const float4*>(wp + j0);
#pragma unroll
    for (int k = 0; k < 4; k++) {
        int sk = (&s.x)[k];
        int dk = dbase + (&d.x)[k];
        float wk = (&w.x)[k];
        int c = atomicAdd(&g_cnt[dk], 1);
        if (c < CAP)
            g_bpack[(size_t)dk * CAP + c] = make_int2(sk, __float_as_int(wk));
    }
}

// ---------------- output transpose + cnt reset for next call ----------------
__global__ void transpose_out_kernel(float* __restrict__ out) {
    if (blockIdx.x == 0 && blockIdx.y == 0) {
        for (int i = threadIdx.y * 32 + threadIdx.x; i < NODES; i += 256)
            g_cnt[i] = 0;
    }
    __shared__ float tile[32][33];
    const int bd = blockIdx.x * 32;
    const int bb = blockIdx.y * 32;
    const int tx = threadIdx.x, ty = threadIdx.y;
#pragma unroll
    for (int i = 0; i < 32; i += 8)
        tile[ty + i][tx] = g_outT[(size_t)(bd + ty + i) * B_ + bb + tx];
    __syncthreads();
#pragma unroll
    for (int i = 0; i < 32; i += 8)
        out[(size_t)(bb + ty + i) * N_OUT + bd + tx] = tile[tx][ty + i];
}

// ---------------- sparse level kernel ----------------
// NSTRIP=2: one CTA per dst, thread owns strips at c0 and c0+2048 (grid (H,1)).
// NSTRIP=1: grid (H,2), thread owns 8 cols in its segment.
// 4-edge unroll for MLP; fp16 values, f32x2 accumulate.
__device__ __forceinline__ void strip_fma(u64* a, u64 W, uint4 v) {
    ffma2(a[0], W, cvt2(v.x));
    ffma2(a[1], W, cvt2(v.y));
    ffma2(a[2], W, cvt2(v.z));
    ffma2(a[3], W, cvt2(v.w));
}

template <int NSTRIP, bool F32OUT>
__global__ void __launch_bounds__(256)
level_kernel(int cbase, __half* __restrict__ outh, float* __restrict__ outf) {
    const int d = blockIdx.x;
    const int t = threadIdx.x;

    int cnt = g_cnt[cbase + d];
    if (cnt > CAP) cnt = CAP;
    const int2* bp = g_bpack + (size_t)(cbase + d) * CAP;

    const int c0 = (NSTRIP == 2) ? t * 8 : blockIdx.y * 2048 + t * 8;
    const __half* __restrict__ nvTh = g_nvTh;

    u64 acc[NSTRIP][4];
#pragma unroll
    for (int s = 0; s < NSTRIP; s++)
#pragma unroll
        for (int j = 0; j < 4; j++) acc[s][j] = 0;

    int e = 0;
    // ---- 4-edge unrolled main loop: 4*NSTRIP independent LDG.128 in flight
    for (; e + 4 <= cnt; e += 4) {
        int4 m0 = *reinterpret_cast<const int4*>(bp + e);       // s0,w0,s1,w1
        int4 m1 = *reinterpret_cast<const int4*>(bp + e + 2);   // s2,w2,s3,w3
        const __half* r0 = nvTh + (size_t)m0.x * B_ + c0;
        const __half* r1 = nvTh + (size_t)m0.z * B_ + c0;
        const __half* r2 = nvTh + (size_t)m1.x * B_ + c0;
        const __half* r3 = nvTh + (size_t)m1.z * B_ + c0;
        uint4 v[4][NSTRIP];
#pragma unroll
        for (int s = 0; s < NSTRIP; s++) {
            v[0][s] = *reinterpret_cast<const uint4*>(r0 + s * 2048);
            v[1][s] = *reinterpret_cast<const uint4*>(r1 + s * 2048);
            v[2][s] = *reinterpret_cast<const uint4*>(r2 + s * 2048);
            v[3][s] = *reinterpret_cast<const uint4*>(r3 + s * 2048);
        }
        u64 W0 = pack2(__int_as_float(m0.y), __int_as_float(m0.y));
        u64 W1 = pack2(__int_as_float(m0.w), __int_as_float(m0.w));
        u64 W2 = pack2(__int_as_float(m1.y), __int_as_float(m1.y));
        u64 W3 = pack2(__int_as_float(m1.w), __int_as_float(m1.w));
#pragma unroll
        for (int s = 0; s < NSTRIP; s++) {
            strip_fma(acc[s], W0, v[0][s]);
            strip_fma(acc[s], W1, v[1][s]);
            strip_fma(acc[s], W2, v[2][s]);
            strip_fma(acc[s], W3, v[3][s]);
        }
    }
    // ---- remainder
    for (; e < cnt; e++) {
        int2 ep = bp[e];
        const __half* r0 = nvTh + (size_t)ep.x * B_ + c0;
        u64 W0 = pack2(__int_as_float(ep.y), __int_as_float(ep.y));
#pragma unroll
        for (int s = 0; s < NSTRIP; s++) {
            uint4 v0 = *reinterpret_cast<const uint4*>(r0 + s * 2048);
            strip_fma(acc[s], W0, v0);
        }
    }

    // ---- relu + store ----
#pragma unroll
    for (int s = 0; s < NSTRIP; s++) {
        float r[8];
#pragma unroll
        for (int j = 0; j < 4; j++) {
            float2 f = unpack2(acc[s][j]);
            r[2 * j]     = fmaxf(f.x, 0.f);
            r[2 * j + 1] = fmaxf(f.y, 0.f);
        }
        const int cc = c0 + s * 2048;
        if (F32OUT) {
            float* p = outf + (size_t)d * B_ + cc;
            *reinterpret_cast<float4*>(p)     = make_float4(r[0], r[1], r[2], r[3]);
            *reinterpret_cast<float4*>(p + 4) = make_float4(r[4], r[5], r[6], r[7]);
        } else {
            uint4 o; __half2 h;
            h = __floats2half2_rn(r[0], r[1]); o.x = *reinterpret_cast<uint32_t*>(&h);
            h = __floats2half2_rn(r[2], r[3]); o.y = *reinterpret_cast<uint32_t*>(&h);
            h = __floats2half2_rn(r[4], r[5]); o.z = *reinterpret_cast<uint32_t*>(&h);
            h = __floats2half2_rn(r[6], r[7]); o.w = *reinterpret_cast<uint32_t*>(&h);
            *reinterpret_cast<uint4*>(outh + (size_t)d * B_ + cc) = o;
        }
    }
}

// ---------------- launch ----------------
extern "C" void kernel_launch(void* const* d_in, const int* in_sizes, int n_in,
                              void* d_out, int out_size) {
    const float* x    = (const float*)d_in[0];
    const int*   src0 = (const int*)  d_in[1];
    const int*   dst0 = (const int*)  d_in[2];
    const float* w0   = (const float*)d_in[3];
    const int*   src1 = (const int*)  d_in[4];
    const int*   dst1 = (const int*)  d_in[5];
    const float* w1   = (const float*)d_in[6];
    const int*   src2 = (const int*)  d_in[7];
    const int*   dst2 = (const int*)  d_in[8];
    const float* w2   = (const float*)d_in[9];
    float* out = (float*)d_out;

    __half* pnvTh; cudaGetSymbolAddress((void**)&pnvTh, g_nvTh);
    float*  poutT; cudaGetSymbolAddress((void**)&poutT, g_outT);

    const int E1 = in_sizes[1], E2 = in_sizes[4], E3 = in_sizes[7];
    const int Etot = E1 + E2 + E3;

    // 1) fused setup: transpose x (fp32->fp16) + build edge buckets
    {
        int bucketBlocks = (Etot + 1023) / 1024;
        setup_kernel<<<TBLOCKS + bucketBlocks, 256>>>(
            x, src0, dst0, w0, E1, src1, dst1, w1, E2, src2, dst2, w2, E3);
    }

    // 2) sparse levels
    //    levels 1/2: one CTA per dst (16 cols/thread), high grid
    level_kernel<2, false><<<H1, 256>>>(0,  pnvTh + (size_t)N_IN * B_,        nullptr);
    level_kernel<2, false><<<H2, 256>>>(H1, pnvTh + (size_t)(N_IN + H1) * B_, nullptr);
    //    level 3: small node count -> 2 segments for occupancy (grid 1024)
    level_kernel<1, true><<<dim3(N_OUT, 2), 256>>>(H1 + H2, nullptr, poutT);

    // 3) transpose result to [B, N_OUT] (+ reset g_cnt for next call)
    transpose_out_kernel<<<dim3(N_OUT / 32, B_ / 32), dim3(32, 8)>>>(out);
}